// round 4
// baseline (speedup 1.0000x reference)
#include <cuda_runtime.h>
#include <cfloat>

// Problem constants (shapes fixed by the reference).
#define ED 128            // embed dim
#define NCODES 10000
#define NCODES_PAD 10048  // ceil(10000/64)*64
#define NSAMPLES 16384
#define TM 64             // samples per block tile
#define TN 64             // codes per chunk

// __device__ scratch (allocations are forbidden).
__device__ float g_cmT[NCODES_PAD * ED];   // transposed codebook [code][dim]  (~5.1 MB)
__device__ float g_c2[NCODES_PAD];         // per-code squared norms (FLT_MAX padding)
__device__ int   g_argmin[NSAMPLES];
__device__ float g_partial[256];

// ---------------------------------------------------------------------------
// Kernel 0: transpose codebook (128 x ncodes -> ncodes x 128) + code norms.
// One block handles 32 codes. 128 threads.
// ---------------------------------------------------------------------------
__global__ void prep_kernel(const float* __restrict__ cm, int ncodes) {
    __shared__ float s[ED][33];   // [dim][code-in-tile], padded
    const int j0  = blockIdx.x * 32;
    const int tid = threadIdx.x;  // 128

    // Load tile: s[d][jj] = cm[d*ncodes + j0+jj]
    for (int idx = tid; idx < ED * 32; idx += 128) {
        int d  = idx >> 5;
        int jj = idx & 31;
        int j  = j0 + jj;
        s[d][jj] = (j < ncodes) ? cm[d * ncodes + j] : 0.0f;
    }
    __syncthreads();

    // Write transposed rows, coalesced over d = tid.
    for (int jj = 0; jj < 32; jj++) {
        int j = j0 + jj;
        if (j < NCODES_PAD) g_cmT[j * ED + tid] = s[tid][jj];
    }

    // Norms (first 32 threads, one code each).
    if (tid < 32) {
        int j = j0 + tid;
        if (j < NCODES_PAD) {
            if (j < ncodes) {
                float acc = 0.0f;
                #pragma unroll 8
                for (int d = 0; d < ED; d++) {
                    float v = s[d][tid];
                    acc = fmaf(v, v, acc);
                }
                g_c2[j] = acc;
            } else {
                g_c2[j] = FLT_MAX;   // padded codes can never win
            }
        }
    }
}

// ---------------------------------------------------------------------------
// Kernel 1: argmin over codes of (||c||^2 - 2 x.c) for each sample.
// Block: 256 threads, TM=64 samples. Loop codes in TN=64 chunks.
// Register blocking: each thread owns 4 samples x 4 codes.
// ---------------------------------------------------------------------------
#define ASTRIDE 132
#define SMEM_FLOATS (TM * ASTRIDE + ED * TN + TN)
#define SMEM_BYTES  (SMEM_FLOATS * 4)

__global__ __launch_bounds__(256) void argmin_kernel(
    const float* __restrict__ x, const float* __restrict__ cm,
    int nsamples, int ncodes)
{
    extern __shared__ float sh[];
    float* As  = sh;                      // [64][132] samples x dims (padded)
    float* Bs  = sh + TM * ASTRIDE;       // [128][64] dims x codes
    float* c2s = Bs + ED * TN;            // [64]

    const int tid = threadIdx.x;
    const int tx  = tid & 15;             // code group (4 codes)
    const int ty  = tid >> 4;             // sample group (4 samples)
    const int s0  = blockIdx.x * TM;

    // Load A tile (64 x 128) once, float4, padded rows.
    for (int t = tid; t < TM * (ED / 4); t += 256) {
        int r  = t >> 5;                  // 32 float4 per row
        int kq = t & 31;
        float4 v = make_float4(0.f, 0.f, 0.f, 0.f);
        if (s0 + r < nsamples)
            v = *reinterpret_cast<const float4*>(x + (size_t)(s0 + r) * ED + kq * 4);
        *reinterpret_cast<float4*>(As + r * ASTRIDE + kq * 4) = v;
    }

    float best[4];
    int   bidx[4];
    #pragma unroll
    for (int i = 0; i < 4; i++) { best[i] = FLT_MAX; bidx[i] = 0; }

    const int nchunks = (ncodes + TN - 1) / TN;
    const float4* cm4 = reinterpret_cast<const float4*>(cm);
    const int nc4 = ncodes >> 2;          // ncodes divisible by 4 (10000)

    for (int ch = 0; ch < nchunks; ch++) {
        const int j0 = ch * TN;
        __syncthreads();                  // protect Bs from previous iteration's readers
        // Load B chunk: Bs[k][j] = cm[k*ncodes + j0+j], 128x64 floats.
        for (int t = tid; t < ED * (TN / 4); t += 256) {
            int k  = t >> 4;              // 16 float4 per row
            int jq = t & 15;
            int j  = j0 + jq * 4;
            float4 v;
            if (j + 3 < ncodes) {
                v = cm4[(size_t)k * nc4 + (j0 >> 2) + jq];
            } else {
                v.x = (j     < ncodes) ? cm[(size_t)k * ncodes + j    ] : 0.0f;
                v.y = (j + 1 < ncodes) ? cm[(size_t)k * ncodes + j + 1] : 0.0f;
                v.z = (j + 2 < ncodes) ? cm[(size_t)k * ncodes + j + 2] : 0.0f;
                v.w = 0.0f;
            }
            *reinterpret_cast<float4*>(Bs + k * TN + jq * 4) = v;
        }
        if (tid < 16) {
            float4 v = *reinterpret_cast<const float4*>(g_c2 + j0 + tid * 4);
            *reinterpret_cast<float4*>(c2s + tid * 4) = v;
        }
        __syncthreads();

        float acc[4][4];
        #pragma unroll
        for (int i = 0; i < 4; i++)
            #pragma unroll
            for (int j = 0; j < 4; j++) acc[i][j] = 0.0f;

        #pragma unroll 4
        for (int k = 0; k < ED; k++) {
            float4 b = *reinterpret_cast<const float4*>(Bs + k * TN + (tx << 2));
            #pragma unroll
            for (int i = 0; i < 4; i++) {
                float a = As[(ty * 4 + i) * ASTRIDE + k];
                acc[i][0] = fmaf(a, b.x, acc[i][0]);
                acc[i][1] = fmaf(a, b.y, acc[i][1]);
                acc[i][2] = fmaf(a, b.z, acc[i][2]);
                acc[i][3] = fmaf(a, b.w, acc[i][3]);
            }
        }

        // score = ||c||^2 - 2 x.c ; strict < keeps earliest index within thread.
        #pragma unroll
        for (int i = 0; i < 4; i++) {
            #pragma unroll
            for (int j = 0; j < 4; j++) {
                float sc = c2s[tx * 4 + j] - 2.0f * acc[i][j];
                int cj = j0 + tx * 4 + j;
                if (sc < best[i]) { best[i] = sc; bidx[i] = cj; }
            }
        }
    }
    __syncthreads();

    // Cross-thread reduce: 16 tx lanes per sample row. Reuse shared memory.
    float* sval = sh;                      // [64][16]
    int*   sidx = reinterpret_cast<int*>(sh + TM * 16);
    #pragma unroll
    for (int i = 0; i < 4; i++) {
        sval[(ty * 4 + i) * 16 + tx] = best[i];
        sidx[(ty * 4 + i) * 16 + tx] = bidx[i];
    }
    __syncthreads();
    if (tid < TM) {
        float bv = FLT_MAX; int bi = 0;
        #pragma unroll
        for (int t = 0; t < 16; t++) {
            float v  = sval[tid * 16 + t];
            int   id = sidx[tid * 16 + t];
            if (v < bv || (v == bv && id < bi)) { bv = v; bi = id; }
        }
        if (s0 + tid < nsamples) g_argmin[s0 + tid] = bi;
    }
}

// ---------------------------------------------------------------------------
// Kernel 2: gather quantized vectors, write output, per-block partial SSE.
// Deterministic: fixed grid-stride order per thread + fixed tree reduce.
// ---------------------------------------------------------------------------
__global__ __launch_bounds__(256) void gather_kernel(
    const float* __restrict__ x, float* __restrict__ out, int total)
{
    __shared__ float red[256];
    const int tid = threadIdx.x;
    float local = 0.0f;
    const int stride = gridDim.x * blockDim.x;
    for (int e = blockIdx.x * blockDim.x + tid; e < total; e += stride) {
        int s = e >> 7;
        int d = e & 127;
        int idx = g_argmin[s];
        float q  = g_cmT[(size_t)idx * ED + d];
        float xv = x[e];
        out[e] = q;
        float diff = q - xv;
        local = fmaf(diff, diff, local);
    }
    red[tid] = local;
    __syncthreads();
    for (int off = 128; off > 0; off >>= 1) {
        if (tid < off) red[tid] += red[tid + off];
        __syncthreads();
    }
    if (tid == 0) g_partial[blockIdx.x] = red[0];
}

// ---------------------------------------------------------------------------
// Kernel 3: final loss = 1.25 * SSE / total, written to d_out[out_size-1].
// ---------------------------------------------------------------------------
__global__ void loss_kernel(float* out, int out_size, int total) {
    __shared__ float red[256];
    const int tid = threadIdx.x;
    red[tid] = g_partial[tid];
    __syncthreads();
    for (int off = 128; off > 0; off >>= 1) {
        if (tid < off) red[tid] += red[tid + off];
        __syncthreads();
    }
    if (tid == 0) out[out_size - 1] = red[0] * 1.25f / (float)total;
}

// ---------------------------------------------------------------------------
extern "C" void kernel_launch(void* const* d_in, const int* in_sizes, int n_in,
                              void* d_out, int out_size) {
    const float* x  = (const float*)d_in[0];   // inputs  (nsamples*128)
    const float* cm = (const float*)d_in[1];   // cluster_mean (128*ncodes)
    float* out = (float*)d_out;

    const int total    = in_sizes[0];
    const int nsamples = total / ED;
    const int ncodes   = in_sizes[1] / ED;

    cudaFuncSetAttribute(argmin_kernel,
                         cudaFuncAttributeMaxDynamicSharedMemorySize, SMEM_BYTES);

    prep_kernel<<<NCODES_PAD / 32, 128>>>(cm, ncodes);
    argmin_kernel<<<(nsamples + TM - 1) / TM, 256, SMEM_BYTES>>>(x, cm, nsamples, ncodes);
    gather_kernel<<<256, 256>>>(x, out, total);
    loss_kernel<<<1, 256>>>(out, out_size, total);
}

// round 12
// speedup vs baseline: 5.0497x; 5.0497x over previous
#include <cuda_runtime.h>
#include <cuda_bf16.h>
#include <cfloat>
#include <cstdint>

// Fixed problem shapes.
#define ED          128
#define NCODES_PAD  10112          // 79 chunks * 128
#define NSAMP_MAX   16384
#define TOPK        16             // 2 warp-halves x 4 lanes x top-2

// ---------------------------------------------------------------------------
// Device scratch (no allocations allowed).
// ---------------------------------------------------------------------------
__device__ float  g_cmT[NCODES_PAD * ED];                 // fp32 transposed codebook [code][dim]
__device__ __align__(16) float g_c2[NCODES_PAD];          // code squared norms (FLT_MAX pads)
__device__ float4 g_cb[NCODES_PAD * ED / 8];              // bf16 codebook [code][dim], 2.6MB
__device__ int    g_cand[NSAMP_MAX * TOPK];
__device__ int    g_argmin[NSAMP_MAX];
__device__ float  g_partial[256];

// ---------------------------------------------------------------------------
// PTX helpers (base-ISA only: no 'a'-suffix features).
// ---------------------------------------------------------------------------
__device__ __forceinline__ uint32_t smem_to_u32(const void* p) {
    uint32_t a;
    asm("{ .reg .u64 t; cvta.to.shared.u64 t, %1; cvt.u32.u64 %0, t; }" : "=r"(a) : "l"(p));
    return a;
}
#define CP_ASYNC16(dst, src) \
    asm volatile("cp.async.cg.shared.global [%0], [%1], 16;" :: "r"(dst), "l"(src) : "memory")
#define CP_COMMIT() asm volatile("cp.async.commit_group;" ::: "memory")
#define CP_WAIT0()  asm volatile("cp.async.wait_group 0;"  ::: "memory")
#define CP_WAIT1()  asm volatile("cp.async.wait_group 1;"  ::: "memory")

__device__ __forceinline__ void ldsm4(uint32_t* r, uint32_t addr) {
    asm volatile("ldmatrix.sync.aligned.m8n8.x4.shared.b16 {%0,%1,%2,%3}, [%4];"
        : "=r"(r[0]), "=r"(r[1]), "=r"(r[2]), "=r"(r[3]) : "r"(addr));
}
__device__ __forceinline__ void mma_bf16(float* d, const uint32_t* a, const uint32_t* b) {
    asm volatile(
        "mma.sync.aligned.m16n8k16.row.col.f32.bf16.bf16.f32 "
        "{%0,%1,%2,%3}, {%4,%5,%6,%7}, {%8,%9}, {%0,%1,%2,%3};"
        : "+f"(d[0]), "+f"(d[1]), "+f"(d[2]), "+f"(d[3])
        : "r"(a[0]), "r"(a[1]), "r"(a[2]), "r"(a[3]), "r"(b[0]), "r"(b[1]));
}

// ---------------------------------------------------------------------------
// Kernel 0: transpose codebook (fp32), bf16 codebook [code][dim], code norms.
// One block per 32 codes. 128 threads (tid = dim).
// ---------------------------------------------------------------------------
__global__ void prep_kernel(const float* __restrict__ cm, int ncodes) {
    __shared__ float s[ED][33];
    const int j0  = blockIdx.x * 32;
    const int tid = threadIdx.x;

    for (int idx = tid; idx < ED * 32; idx += 128) {
        int d  = idx >> 5;
        int jj = idx & 31;
        int j  = j0 + jj;
        s[d][jj] = (j < ncodes) ? cm[d * ncodes + j] : 0.0f;
    }
    __syncthreads();

    __nv_bfloat16* cb = reinterpret_cast<__nv_bfloat16*>(g_cb);
    for (int jj = 0; jj < 32; jj++) {
        int j = j0 + jj;
        float v = s[tid][jj];
        g_cmT[(size_t)j * ED + tid] = v;
        cb[(size_t)j * ED + tid] = __float2bfloat16(v);
    }

    if (tid < 32) {
        int j = j0 + tid;
        if (j < ncodes) {
            float acc = 0.0f;
            #pragma unroll 8
            for (int d = 0; d < ED; d++) { float v = s[d][tid]; acc = fmaf(v, v, acc); }
            g_c2[j] = acc;
        } else {
            g_c2[j] = FLT_MAX;   // padded codes can never win
        }
    }
}

// ---------------------------------------------------------------------------
// Kernel 1: bf16 mma.sync GEMM + per-lane top-2 approximate screen.
// 256 threads = 8 warps, laid out 4 (M) x 2 (N). CTA tile: 128 samples.
// Per chunk: 128 codes. Warp tile: 32 (M) x 64 (N), m16n8k16 fragments.
// SMEM rows padded to 272B (17 x 16B) for conflict-free ldmatrix.
// Each sample row is covered by 2 warps (wn=0, wn=64); each writes its OWN
// 8-slot half of g_cand (slots (wid>>2)*8 .. +7) -- no overwrite.
// ---------------------------------------------------------------------------
#define ROWB     272                          // bytes per 128-bf16 row, padded
#define SM_A     0                            // 128 * 272 = 34816
#define SM_B0    34816
#define SM_B1    69632
#define SM_C2    104448                       // 2 x 512B
#define SM_TOTAL 105472

__global__ __launch_bounds__(256, 1) void argmin_mma_kernel(
    const float* __restrict__ x, int nsamples, int ncodes)
{
    extern __shared__ char smem[];
    const uint32_t smem_base = smem_to_u32(smem);
    const int tid = threadIdx.x;
    const int wid = tid >> 5;
    const int lid = tid & 31;
    const int wm  = (wid & 3) * 32;        // warp M base (samples)
    const int wh  = wid >> 2;              // warp N half (0 or 1)
    const int wn  = wh * 64;               // warp N base (codes within chunk)
    const int s0  = blockIdx.x * 128;
    const int nchunks = (ncodes + 127) >> 7;

    // --- A tile: fp32 -> bf16 into padded SMEM rows ---
    for (int t = tid; t < 128 * 64; t += 256) {
        int r = t >> 6, k = (t & 63) << 1;
        float2 v = make_float2(0.f, 0.f);
        if (s0 + r < nsamples)
            v = *reinterpret_cast<const float2*>(x + (size_t)(s0 + r) * ED + k);
        __nv_bfloat162 h;
        h.x = __float2bfloat16(v.x);
        h.y = __float2bfloat16(v.y);
        *reinterpret_cast<__nv_bfloat162*>(smem + SM_A + r * ROWB + k * 2) = h;
    }

    auto copy_chunk = [&](int ch, int buf) {
        const char* src = reinterpret_cast<const char*>(g_cb) + (size_t)ch * 32768;
        uint32_t dst = smem_base + (buf ? SM_B1 : SM_B0);
        #pragma unroll
        for (int i = 0; i < 8; i++) {
            int idx = tid + i * 256;               // 0..2047 16B chunks
            int row = idx >> 4, c16 = idx & 15;
            CP_ASYNC16(dst + (uint32_t)(row * ROWB + c16 * 16), src + idx * 16);
        }
        if (tid < 32) {
            const char* s2 = reinterpret_cast<const char*>(g_c2 + (ch << 7)) + tid * 16;
            CP_ASYNC16(smem_base + SM_C2 + (uint32_t)(buf * 512 + tid * 16), s2);
        }
        CP_COMMIT();
    };

    // Prologue copies (A-store -> ldmatrix ordering handled by the loop's syncthreads).
    copy_chunk(0, 0);
    if (nchunks > 1) copy_chunk(1, 1);

    // ldmatrix lane address offsets.
    const uint32_t aBase = smem_base + SM_A +
        (uint32_t)((wm + (lid & 15)) * ROWB + ((lid >> 4) << 4));
    const uint32_t boff =
        (uint32_t)((wn + (lid & 7) + ((lid >> 4) & 1) * 8) * ROWB + (((lid >> 3) & 1) << 4));

    // Per-lane top-2 for 4 row-streams (2 m-tiles x 2 row-halves).
    float tv0[4], tv1[4];
    int   ti0[4], ti1[4];
    #pragma unroll
    for (int st = 0; st < 4; st++) { tv0[st] = tv1[st] = FLT_MAX; ti0[st] = ti1[st] = 0; }

    auto upd2 = [&](int st, float sc, int j) {
        bool lt1 = sc < tv1[st];
        bool lt0 = sc < tv0[st];
        if (lt1) {
            tv1[st] = lt0 ? tv0[st] : sc;
            ti1[st] = lt0 ? ti0[st] : j;
            if (lt0) { tv0[st] = sc; ti0[st] = j; }
        }
    };

    for (int ch = 0; ch < nchunks; ch++) {
        if (ch + 1 < nchunks) CP_WAIT1(); else CP_WAIT0();
        __syncthreads();                      // B[ch] (+c2) visible to all warps

        const uint32_t bBase = smem_base + ((ch & 1) ? SM_B1 : SM_B0) + boff;

        float acc[2][8][4];
        #pragma unroll
        for (int mt = 0; mt < 2; mt++)
            #pragma unroll
            for (int nt = 0; nt < 8; nt++)
                #pragma unroll
                for (int e = 0; e < 4; e++) acc[mt][nt][e] = 0.0f;

        #pragma unroll
        for (int ks = 0; ks < 8; ks++) {
            uint32_t a[2][4];
            ldsm4(a[0], aBase + ks * 32);
            ldsm4(a[1], aBase + 16 * ROWB + ks * 32);
            #pragma unroll
            for (int p = 0; p < 4; p++) {
                uint32_t b[4];
                ldsm4(b, bBase + p * 16 * ROWB + ks * 32);
                mma_bf16(acc[0][2 * p],     a[0], b);
                mma_bf16(acc[0][2 * p + 1], a[0], b + 2);
                mma_bf16(acc[1][2 * p],     a[1], b);
                mma_bf16(acc[1][2 * p + 1], a[1], b + 2);
            }
        }

        // Epilogue: score = ||c||^2 - 2 x.c; top-2 per row stream.
        const float2* c2p = reinterpret_cast<const float2*>(smem + SM_C2 + (ch & 1) * 512);
        const int cb = wn + 2 * (lid & 3);
        const int jb = (ch << 7) + cb;
        #pragma unroll
        for (int nt = 0; nt < 8; nt++) {
            float2 c2 = c2p[(cb + nt * 8) >> 1];
            int j = jb + nt * 8;
            upd2(0, fmaf(-2.0f, acc[0][nt][0], c2.x), j);
            upd2(0, fmaf(-2.0f, acc[0][nt][1], c2.y), j + 1);
            upd2(1, fmaf(-2.0f, acc[0][nt][2], c2.x), j);
            upd2(1, fmaf(-2.0f, acc[0][nt][3], c2.y), j + 1);
            upd2(2, fmaf(-2.0f, acc[1][nt][0], c2.x), j);
            upd2(2, fmaf(-2.0f, acc[1][nt][1], c2.y), j + 1);
            upd2(3, fmaf(-2.0f, acc[1][nt][2], c2.x), j);
            upd2(3, fmaf(-2.0f, acc[1][nt][3], c2.y), j + 1);
        }

        __syncthreads();                      // all reads of buf (ch&1) done
        if (ch + 2 < nchunks) copy_chunk(ch + 2, ch & 1);
    }

    // Write candidates. Sample row gets 16 slots: warp-half wh owns slots
    // wh*8 + q*2 + {0,1}; the 4 lanes sharing a row (q = lid&3) fill them.
    const int g = lid >> 2, q = lid & 3;
    #pragma unroll
    for (int st = 0; st < 4; st++) {
        int row = wm + (st >> 1) * 16 + (st & 1) * 8 + g;
        int s = s0 + row;
        if (s < nsamples) {
            g_cand[s * TOPK + wh * 8 + q * 2 + 0] = ti0[st];
            g_cand[s * TOPK + wh * 8 + q * 2 + 1] = ti1[st];
        }
    }
}

// ---------------------------------------------------------------------------
// Kernel 2: exact fp32 rescore of the 16 candidates. One warp per sample.
// ---------------------------------------------------------------------------
__global__ __launch_bounds__(256) void rescore_kernel(const float* __restrict__ x, int nsamples) {
    const int gw   = (blockIdx.x * blockDim.x + threadIdx.x) >> 5;
    const int lane = threadIdx.x & 31;
    if (gw >= nsamples) return;
    const float4 xv = *reinterpret_cast<const float4*>(x + (size_t)gw * ED + lane * 4);
    float best = FLT_MAX;
    int   bi   = 0x7fffffff;
    #pragma unroll 1
    for (int c = 0; c < TOPK; c++) {
        int idx = g_cand[gw * TOPK + c];
        const float4 cv = *reinterpret_cast<const float4*>(g_cmT + (size_t)idx * ED + lane * 4);
        float p = xv.x * cv.x;
        p = fmaf(xv.y, cv.y, p);
        p = fmaf(xv.z, cv.z, p);
        p = fmaf(xv.w, cv.w, p);
        #pragma unroll
        for (int o = 16; o > 0; o >>= 1) p += __shfl_xor_sync(0xffffffffu, p, o);
        float d = fmaf(-2.0f, p, g_c2[idx]);
        if (d < best || (d == best && idx < bi)) { best = d; bi = idx; }
    }
    if (lane == 0) g_argmin[gw] = bi;
}

// ---------------------------------------------------------------------------
// Kernel 3: gather quantized vectors (float4), write output + partial SSE.
// ---------------------------------------------------------------------------
__global__ __launch_bounds__(256) void gather_kernel(
    const float* __restrict__ x, float* __restrict__ out, int total)
{
    __shared__ float red[256];
    const int tid = threadIdx.x;
    float local = 0.0f;
    const int total4 = total >> 2;
    const int stride = gridDim.x * blockDim.x;
    for (int e = blockIdx.x * blockDim.x + tid; e < total4; e += stride) {
        int s = e >> 5, d4 = e & 31;
        int idx = g_argmin[s];
        float4 q  = *reinterpret_cast<const float4*>(g_cmT + (size_t)idx * ED + d4 * 4);
        float4 xv = *reinterpret_cast<const float4*>(x + (size_t)e * 4);
        *reinterpret_cast<float4*>(out + (size_t)e * 4) = q;
        float dx = q.x - xv.x, dy = q.y - xv.y, dz = q.z - xv.z, dw = q.w - xv.w;
        local = fmaf(dx, dx, local);
        local = fmaf(dy, dy, local);
        local = fmaf(dz, dz, local);
        local = fmaf(dw, dw, local);
    }
    red[tid] = local;
    __syncthreads();
    for (int off = 128; off > 0; off >>= 1) {
        if (tid < off) red[tid] += red[tid + off];
        __syncthreads();
    }
    if (tid == 0) g_partial[blockIdx.x] = red[0];
}

// ---------------------------------------------------------------------------
// Kernel 4: final loss = 1.25 * SSE / total.
// ---------------------------------------------------------------------------
__global__ void loss_kernel(float* out, int out_size, int total) {
    __shared__ float red[256];
    const int tid = threadIdx.x;
    red[tid] = g_partial[tid];
    __syncthreads();
    for (int off = 128; off > 0; off >>= 1) {
        if (tid < off) red[tid] += red[tid + off];
        __syncthreads();
    }
    if (tid == 0) out[out_size - 1] = red[0] * 1.25f / (float)total;
}

// ---------------------------------------------------------------------------
extern "C" void kernel_launch(void* const* d_in, const int* in_sizes, int n_in,
                              void* d_out, int out_size) {
    const float* x  = (const float*)d_in[0];   // inputs (nsamples * 128)
    const float* cm = (const float*)d_in[1];   // cluster_mean (128 * ncodes)
    float* out = (float*)d_out;

    const int total    = in_sizes[0];
    const int nsamples = total / ED;
    const int ncodes   = in_sizes[1] / ED;

    cudaFuncSetAttribute(argmin_mma_kernel,
                         cudaFuncAttributeMaxDynamicSharedMemorySize, SM_TOTAL);

    prep_kernel<<<NCODES_PAD / 32, 128>>>(cm, ncodes);
    argmin_mma_kernel<<<(nsamples + 127) / 128, 256, SM_TOTAL>>>(x, nsamples, ncodes);
    rescore_kernel<<<(nsamples * 32 + 255) / 256, 256>>>(x, nsamples);
    gather_kernel<<<256, 256>>>(x, out, total);
    loss_kernel<<<1, 256>>>(out, out_size, total);
}

// round 13
// speedup vs baseline: 5.1920x; 1.0282x over previous
#include <cuda_runtime.h>
#include <cuda_fp16.h>
#include <cfloat>
#include <cstdint>

// Fixed problem shapes.
#define ED          128
#define NCODES_PAD  10240          // 40 chunks * 256
#define NSAMP_MAX   16384
#define TOPK        16             // 2 warp-halves x 4 lanes x top-2

// ---------------------------------------------------------------------------
// Device scratch (no allocations allowed).
// ---------------------------------------------------------------------------
__device__ float  g_cmT[NCODES_PAD * ED];                 // fp32 transposed codebook [code][dim]
__device__ __align__(16) float g_c2[NCODES_PAD];          // code squared norms (FLT_MAX pads)
__device__ float4 g_cb[NCODES_PAD * ED / 8];              // fp16 codebook [code][dim], 2.6MB
__device__ int    g_cand[NSAMP_MAX * TOPK];
__device__ int    g_argmin[NSAMP_MAX];
__device__ float  g_partial[256];

// ---------------------------------------------------------------------------
// PTX helpers (base-ISA only: no 'a'-suffix features).
// ---------------------------------------------------------------------------
__device__ __forceinline__ uint32_t smem_to_u32(const void* p) {
    uint32_t a;
    asm("{ .reg .u64 t; cvta.to.shared.u64 t, %1; cvt.u32.u64 %0, t; }" : "=r"(a) : "l"(p));
    return a;
}
#define CP_ASYNC16(dst, src) \
    asm volatile("cp.async.cg.shared.global [%0], [%1], 16;" :: "r"(dst), "l"(src) : "memory")
#define CP_COMMIT() asm volatile("cp.async.commit_group;" ::: "memory")
#define CP_WAIT0()  asm volatile("cp.async.wait_group 0;"  ::: "memory")
#define CP_WAIT1()  asm volatile("cp.async.wait_group 1;"  ::: "memory")

__device__ __forceinline__ void ldsm4(uint32_t* r, uint32_t addr) {
    asm volatile("ldmatrix.sync.aligned.m8n8.x4.shared.b16 {%0,%1,%2,%3}, [%4];"
        : "=r"(r[0]), "=r"(r[1]), "=r"(r[2]), "=r"(r[3]) : "r"(addr));
}
// fp16 in, fp16 accumulate (2 packed-half regs for D).
__device__ __forceinline__ void mma_f16(uint32_t* d, const uint32_t* a, const uint32_t* b) {
    asm volatile(
        "mma.sync.aligned.m16n8k16.row.col.f16.f16.f16.f16 "
        "{%0,%1}, {%2,%3,%4,%5}, {%6,%7}, {%0,%1};"
        : "+r"(d[0]), "+r"(d[1])
        : "r"(a[0]), "r"(a[1]), "r"(a[2]), "r"(a[3]), "r"(b[0]), "r"(b[1]));
}

// ---------------------------------------------------------------------------
// Kernel 0: transpose codebook (fp32), fp16 codebook [code][dim], code norms.
// One block per 32 codes. 128 threads (tid = dim).
// ---------------------------------------------------------------------------
__global__ void prep_kernel(const float* __restrict__ cm, int ncodes) {
    __shared__ float s[ED][33];
    const int j0  = blockIdx.x * 32;
    const int tid = threadIdx.x;

    for (int idx = tid; idx < ED * 32; idx += 128) {
        int d  = idx >> 5;
        int jj = idx & 31;
        int j  = j0 + jj;
        s[d][jj] = (j < ncodes) ? cm[d * ncodes + j] : 0.0f;
    }
    __syncthreads();

    __half* cb = reinterpret_cast<__half*>(g_cb);
    for (int jj = 0; jj < 32; jj++) {
        int j = j0 + jj;
        float v = s[tid][jj];
        g_cmT[(size_t)j * ED + tid] = v;
        cb[(size_t)j * ED + tid] = __float2half(v);
    }

    if (tid < 32) {
        int j = j0 + tid;
        if (j < ncodes) {
            float acc = 0.0f;
            #pragma unroll 8
            for (int d = 0; d < ED; d++) { float v = s[d][tid]; acc = fmaf(v, v, acc); }
            g_c2[j] = acc;
        } else {
            g_c2[j] = FLT_MAX;   // padded codes can never win
        }
    }
}

// ---------------------------------------------------------------------------
// Kernel 1: fp16 mma.sync GEMM + per-lane top-2 approximate screen.
// 256 threads = 8 warps, 4 (M) x 2 (N). CTA tile: 128 samples.
// Per chunk: 256 codes. Warp tile: 32 (M) x 128 (N), m16n8k16 f16-acc frags.
// SMEM rows padded to 272B (17 x 16B) for conflict-free ldmatrix.
// Each sample row covered by 2 warps (wn=0/128); disjoint g_cand slot halves.
// ---------------------------------------------------------------------------
#define ROWB     272                          // bytes per 128-fp16 row, padded
#define SM_A     0                            // 128 * 272 = 34816
#define SM_B0    34816                        // 256 * 272 = 69632 per buffer
#define SM_B1    104448
#define SM_C2    174080                       // 2 x 1024B
#define SM_TOTAL 176128

__global__ __launch_bounds__(256, 1) void argmin_mma_kernel(
    const float* __restrict__ x, int nsamples, int ncodes)
{
    extern __shared__ char smem[];
    const uint32_t smem_base = smem_to_u32(smem);
    const int tid = threadIdx.x;
    const int wid = tid >> 5;
    const int lid = tid & 31;
    const int wm  = (wid & 3) * 32;        // warp M base (samples)
    const int wh  = wid >> 2;              // warp N half (0 or 1)
    const int wn  = wh * 128;              // warp N base (codes within chunk)
    const int s0  = blockIdx.x * 128;
    const int nchunks = (ncodes + 255) >> 8;

    // --- A tile: fp32 -> fp16 into padded SMEM rows ---
    for (int t = tid; t < 128 * 64; t += 256) {
        int r = t >> 6, k = (t & 63) << 1;
        float2 v = make_float2(0.f, 0.f);
        if (s0 + r < nsamples)
            v = *reinterpret_cast<const float2*>(x + (size_t)(s0 + r) * ED + k);
        *reinterpret_cast<__half2*>(smem + SM_A + r * ROWB + k * 2) = __float22half2_rn(v);
    }

    auto copy_chunk = [&](int ch, int buf) {
        const char* src = reinterpret_cast<const char*>(g_cb) + (size_t)ch * 65536;
        uint32_t dst = smem_base + (buf ? SM_B1 : SM_B0);
        #pragma unroll
        for (int i = 0; i < 16; i++) {
            int idx = tid + i * 256;               // 0..4095 16B units
            int row = idx >> 4, c16 = idx & 15;
            CP_ASYNC16(dst + (uint32_t)(row * ROWB + c16 * 16), src + idx * 16);
        }
        if (tid < 64) {
            const char* s2 = reinterpret_cast<const char*>(g_c2 + (ch << 8)) + tid * 16;
            CP_ASYNC16(smem_base + SM_C2 + (uint32_t)(buf * 1024 + tid * 16), s2);
        }
        CP_COMMIT();
    };

    copy_chunk(0, 0);
    if (nchunks > 1) copy_chunk(1, 1);

    // ldmatrix lane address offsets.
    const uint32_t aBase = smem_base + SM_A +
        (uint32_t)((wm + (lid & 15)) * ROWB + ((lid >> 4) << 4));
    const uint32_t boff =
        (uint32_t)((wn + (lid & 7) + ((lid >> 4) & 1) * 8) * ROWB + (((lid >> 3) & 1) << 4));

    // Per-lane top-2 for 4 row-streams (2 m-tiles x 2 row-halves).
    float tv0[4], tv1[4];
    int   ti0[4], ti1[4];
    #pragma unroll
    for (int st = 0; st < 4; st++) { tv0[st] = tv1[st] = FLT_MAX; ti0[st] = ti1[st] = 0; }

    auto upd2 = [&](int st, float sc, int j) {
        bool lt1 = sc < tv1[st];
        bool lt0 = sc < tv0[st];
        if (lt1) {
            tv1[st] = lt0 ? tv0[st] : sc;
            ti1[st] = lt0 ? ti0[st] : j;
            if (lt0) { tv0[st] = sc; ti0[st] = j; }
        }
    };

    for (int ch = 0; ch < nchunks; ch++) {
        if (ch + 1 < nchunks) CP_WAIT1(); else CP_WAIT0();
        __syncthreads();                      // B[ch] (+c2) visible to all warps

        const uint32_t bBase = smem_base + ((ch & 1) ? SM_B1 : SM_B0) + boff;

        uint32_t acc[2][16][2];               // fp16x2 accumulators
        #pragma unroll
        for (int mt = 0; mt < 2; mt++)
            #pragma unroll
            for (int nt = 0; nt < 16; nt++) { acc[mt][nt][0] = 0u; acc[mt][nt][1] = 0u; }

        #pragma unroll
        for (int ks = 0; ks < 8; ks++) {
            uint32_t a[2][4];
            ldsm4(a[0], aBase + ks * 32);
            ldsm4(a[1], aBase + 16 * ROWB + ks * 32);
            #pragma unroll
            for (int p = 0; p < 8; p++) {
                uint32_t b[4];
                ldsm4(b, bBase + p * 16 * ROWB + ks * 32);
                mma_f16(acc[0][2 * p],     a[0], b);
                mma_f16(acc[0][2 * p + 1], a[0], b + 2);
                mma_f16(acc[1][2 * p],     a[1], b);
                mma_f16(acc[1][2 * p + 1], a[1], b + 2);
            }
        }

        // Epilogue: score = ||c||^2 - 2 x.c; top-2 per row stream.
        // f16-acc D layout: reg0 = row g, cols {2q, 2q+1} packed; reg1 = row g+8.
        const float2* c2p = reinterpret_cast<const float2*>(smem + SM_C2 + (ch & 1) * 1024);
        const int cb = wn + 2 * (lid & 3);
        const int jb = (ch << 8) + cb;
        #pragma unroll
        for (int nt = 0; nt < 16; nt++) {
            float2 c2 = c2p[(cb + nt * 8) >> 1];
            int j = jb + nt * 8;
            float2 f;
            f = __half22float2(*reinterpret_cast<__half2*>(&acc[0][nt][0]));
            upd2(0, fmaf(-2.0f, f.x, c2.x), j);
            upd2(0, fmaf(-2.0f, f.y, c2.y), j + 1);
            f = __half22float2(*reinterpret_cast<__half2*>(&acc[0][nt][1]));
            upd2(1, fmaf(-2.0f, f.x, c2.x), j);
            upd2(1, fmaf(-2.0f, f.y, c2.y), j + 1);
            f = __half22float2(*reinterpret_cast<__half2*>(&acc[1][nt][0]));
            upd2(2, fmaf(-2.0f, f.x, c2.x), j);
            upd2(2, fmaf(-2.0f, f.y, c2.y), j + 1);
            f = __half22float2(*reinterpret_cast<__half2*>(&acc[1][nt][1]));
            upd2(3, fmaf(-2.0f, f.x, c2.x), j);
            upd2(3, fmaf(-2.0f, f.y, c2.y), j + 1);
        }

        __syncthreads();                      // all reads of buf (ch&1) done
        if (ch + 2 < nchunks) copy_chunk(ch + 2, ch & 1);
    }

    // Write candidates: warp-half wh owns slots wh*8 + q*2 + {0,1}.
    const int g = lid >> 2, q = lid & 3;
    #pragma unroll
    for (int st = 0; st < 4; st++) {
        int row = wm + (st >> 1) * 16 + (st & 1) * 8 + g;
        int s = s0 + row;
        if (s < nsamples) {
            g_cand[s * TOPK + wh * 8 + q * 2 + 0] = ti0[st];
            g_cand[s * TOPK + wh * 8 + q * 2 + 1] = ti1[st];
        }
    }
}

// ---------------------------------------------------------------------------
// Kernel 2: exact fp32 rescore of the 16 candidates. One warp per sample.
// ---------------------------------------------------------------------------
__global__ __launch_bounds__(256) void rescore_kernel(const float* __restrict__ x, int nsamples) {
    const int gw   = (blockIdx.x * blockDim.x + threadIdx.x) >> 5;
    const int lane = threadIdx.x & 31;
    if (gw >= nsamples) return;
    const float4 xv = *reinterpret_cast<const float4*>(x + (size_t)gw * ED + lane * 4);
    float best = FLT_MAX;
    int   bi   = 0x7fffffff;
    #pragma unroll 1
    for (int c = 0; c < TOPK; c++) {
        int idx = g_cand[gw * TOPK + c];
        const float4 cv = *reinterpret_cast<const float4*>(g_cmT + (size_t)idx * ED + lane * 4);
        float p = xv.x * cv.x;
        p = fmaf(xv.y, cv.y, p);
        p = fmaf(xv.z, cv.z, p);
        p = fmaf(xv.w, cv.w, p);
        #pragma unroll
        for (int o = 16; o > 0; o >>= 1) p += __shfl_xor_sync(0xffffffffu, p, o);
        float d = fmaf(-2.0f, p, g_c2[idx]);
        if (d < best || (d == best && idx < bi)) { best = d; bi = idx; }
    }
    if (lane == 0) g_argmin[gw] = bi;
}

// ---------------------------------------------------------------------------
// Kernel 3: gather quantized vectors (float4), write output + partial SSE.
// ---------------------------------------------------------------------------
__global__ __launch_bounds__(256) void gather_kernel(
    const float* __restrict__ x, float* __restrict__ out, int total)
{
    __shared__ float red[256];
    const int tid = threadIdx.x;
    float local = 0.0f;
    const int total4 = total >> 2;
    const int stride = gridDim.x * blockDim.x;
    for (int e = blockIdx.x * blockDim.x + tid; e < total4; e += stride) {
        int s = e >> 5, d4 = e & 31;
        int idx = g_argmin[s];
        float4 q  = *reinterpret_cast<const float4*>(g_cmT + (size_t)idx * ED + d4 * 4);
        float4 xv = *reinterpret_cast<const float4*>(x + (size_t)e * 4);
        *reinterpret_cast<float4*>(out + (size_t)e * 4) = q;
        float dx = q.x - xv.x, dy = q.y - xv.y, dz = q.z - xv.z, dw = q.w - xv.w;
        local = fmaf(dx, dx, local);
        local = fmaf(dy, dy, local);
        local = fmaf(dz, dz, local);
        local = fmaf(dw, dw, local);
    }
    red[tid] = local;
    __syncthreads();
    for (int off = 128; off > 0; off >>= 1) {
        if (tid < off) red[tid] += red[tid + off];
        __syncthreads();
    }
    if (tid == 0) g_partial[blockIdx.x] = red[0];
}

// ---------------------------------------------------------------------------
// Kernel 4: final loss = 1.25 * SSE / total.
// ---------------------------------------------------------------------------
__global__ void loss_kernel(float* out, int out_size, int total) {
    __shared__ float red[256];
    const int tid = threadIdx.x;
    red[tid] = g_partial[tid];
    __syncthreads();
    for (int off = 128; off > 0; off >>= 1) {
        if (tid < off) red[tid] += red[tid + off];
        __syncthreads();
    }
    if (tid == 0) out[out_size - 1] = red[0] * 1.25f / (float)total;
}

// ---------------------------------------------------------------------------
extern "C" void kernel_launch(void* const* d_in, const int* in_sizes, int n_in,
                              void* d_out, int out_size) {
    const float* x  = (const float*)d_in[0];   // inputs (nsamples * 128)
    const float* cm = (const float*)d_in[1];   // cluster_mean (128 * ncodes)
    float* out = (float*)d_out;

    const int total    = in_sizes[0];
    const int nsamples = total / ED;
    const int ncodes   = in_sizes[1] / ED;

    cudaFuncSetAttribute(argmin_mma_kernel,
                         cudaFuncAttributeMaxDynamicSharedMemorySize, SM_TOTAL);

    prep_kernel<<<NCODES_PAD / 32, 128>>>(cm, ncodes);
    argmin_mma_kernel<<<(nsamples + 127) / 128, 256, SM_TOTAL>>>(x, nsamples, ncodes);
    rescore_kernel<<<(nsamples * 32 + 255) / 256, 256>>>(x, nsamples);
    gather_kernel<<<256, 256>>>(x, out, total);
    loss_kernel<<<1, 256>>>(out, out_size, total);
}